// round 1
// baseline (speedup 1.0000x reference)
#include <cuda_runtime.h>
#include <math.h>

#define VV 50257
#define EE 300
#define HH 600
#define HD 300
#define LL 60
#define ZZ 100
#define T_IN 48
#define T_OUT 60
#define EOS_TOK 1

#define OFF_MEAN (T_OUT * VV)
#define OFF_LOGV (OFF_MEAN + LL * ZZ)

#define P_CTAS 120
#define P_THREADS 256
#define P_WARPS (P_CTAS * (P_THREADS / 32))

// ---------------- device scratch (static: no allocation allowed) ----------------
__device__ float g_h[2][2][HD];            // [pingpong][dir][HD]
__device__ float g_enc_gi[2][T_IN * 900];  // [dir][t*900+row]  Wih@x + bih
__device__ float g_enc_out[LL * HH];       // zero-padded to L rows
__device__ float g_z[LL * ZZ];
__device__ float g_lat[LL * HH];
__device__ float g_M[LL * EE];             // latent_out @ comb_W[:,300:].T
__device__ float g_combW_app[EE * HH];     // comb_W[:,300:900] repacked
__device__ float g_attn_x[T_OUT * LL];     // attn_W[:, :300]@x_t + attn_b
__device__ float g_comb_x[T_OUT * EE];     // comb_W[:, :300]@x_t + comb_b
__device__ float g_s[LL];
__device__ float g_gh[2][900];
__device__ float g_o[EE];
__device__ float g_hcat[T_OUT * HH];
__device__ float g_logits[T_OUT * VV];     // ~12 MB
__device__ unsigned g_bar;

// ---------------- helpers ----------------
__device__ __forceinline__ float wsum(float v) {
#pragma unroll
    for (int o = 16; o; o >>= 1) v += __shfl_xor_sync(0xffffffffu, v, o);
    return v;
}
__device__ __forceinline__ float wmax(float v) {
#pragma unroll
    for (int o = 16; o; o >>= 1) v = fmaxf(v, __shfl_xor_sync(0xffffffffu, v, o));
    return v;
}
__device__ __forceinline__ float sigm(float x) { return 1.0f / (1.0f + expf(-x)); }

// grid barrier: monotonic counter, reset by init kernel each launch.
// Grid is a single wave (P_CTAS=120 <= 148 SMs, 256 thr, no smem) -> co-resident.
__device__ __forceinline__ void gbar(unsigned& tgt) {
    __syncthreads();
    if (threadIdx.x == 0) {
        __threadfence();
        atomicAdd(&g_bar, 1u);
        tgt += P_CTAS;
        while (atomicAdd(&g_bar, 0u) < tgt) {}
        __threadfence();
    }
    __syncthreads();
}

// ---------------- init ----------------
__global__ void init_kernel() {
    int tid = threadIdx.x;
    if (tid == 0) g_bar = 0u;
    for (int i = tid; i < 2 * 2 * HD; i += blockDim.x) (&g_h[0][0][0])[i] = 0.0f;
    for (int i = tid; i < (LL - T_IN) * HH; i += blockDim.x) g_enc_out[T_IN * HH + i] = 0.0f;
}

__global__ void copy_combW_kernel(const float* __restrict__ comb_W) {
    int i = blockIdx.x * blockDim.x + threadIdx.x;
    if (i < EE * HH) {
        int e = i / HH, h = i % HH;
        g_combW_app[i] = comb_W[e * 900 + EE + h];
    }
}

// ---------------- prepass: one warp per dot task ----------------
#define N_TASKS 108000
__global__ void prepass_kernel(
    const int* __restrict__ input, const int* __restrict__ target,
    const float* __restrict__ emb,
    const float* __restrict__ encWih_f, const float* __restrict__ encbih_f,
    const float* __restrict__ encWih_b, const float* __restrict__ encbih_b,
    const float* __restrict__ attn_W, const float* __restrict__ attn_b,
    const float* __restrict__ comb_W, const float* __restrict__ comb_b)
{
    int gw = blockIdx.x * (blockDim.x >> 5) + (threadIdx.x >> 5);
    int lane = threadIdx.x & 31;
    if (gw >= N_TASKS) return;

    if (gw < 86400) {                       // enc gi = Wih @ emb[tok] + bih
        int dir = gw / 43200;
        int r = gw % 43200;
        int t = r / 900;
        int row = r % 900;
        const float* W = dir ? encWih_b : encWih_f;
        const float* bi = dir ? encbih_b : encbih_f;
        const float* x = emb + (long)input[t] * EE;
        const float* wr = W + row * EE;
        float a = 0.0f;
        for (int k = lane; k < EE; k += 32) a += wr[k] * x[k];
        a = wsum(a);
        if (lane == 0) g_enc_gi[dir][t * 900 + row] = a + bi[row];
    } else if (gw < 90000) {                // attn x-part
        int idx = gw - 86400;
        int t = idx / LL;
        int l = idx % LL;
        int tok = (t == 0) ? EOS_TOK : target[t - 1];
        const float* x = emb + (long)tok * EE;
        const float* wr = attn_W + l * 900;
        float a = 0.0f;
        for (int k = lane; k < EE; k += 32) a += wr[k] * x[k];
        a = wsum(a);
        if (lane == 0) g_attn_x[t * LL + l] = a + attn_b[l];
    } else {                                // comb x-part
        int idx = gw - 90000;
        int t = idx / EE;
        int e = idx % EE;
        int tok = (t == 0) ? EOS_TOK : target[t - 1];
        const float* x = emb + (long)tok * EE;
        const float* wr = comb_W + e * 900;
        float a = 0.0f;
        for (int k = lane; k < EE; k += 32) a += wr[k] * x[k];
        a = wsum(a);
        if (lane == 0) g_comb_x[t * EE + e] = a + comb_b[e];
    }
}

// ---------------- persistent sequential kernel ----------------
__global__ __launch_bounds__(P_THREADS, 1) void seq_kernel(
    const float* __restrict__ eps,
    const float* __restrict__ encWhh_f, const float* __restrict__ encbhh_f,
    const float* __restrict__ encWhh_b, const float* __restrict__ encbhh_b,
    const float* __restrict__ decWih_f, const float* __restrict__ decWhh_f,
    const float* __restrict__ decbih_f, const float* __restrict__ decbhh_f,
    const float* __restrict__ decWih_b, const float* __restrict__ decWhh_b,
    const float* __restrict__ decbih_b, const float* __restrict__ decbhh_b,
    const float* __restrict__ h2m_W, const float* __restrict__ h2m_b,
    const float* __restrict__ h2v_W, const float* __restrict__ h2v_b,
    const float* __restrict__ l2h_W, const float* __restrict__ l2h_b,
    const float* __restrict__ attn_W,
    float* __restrict__ out)
{
    const int lane = threadIdx.x & 31;
    const int gw = blockIdx.x * (P_THREADS >> 5) + (threadIdx.x >> 5);
    unsigned tgt = 0;

    // ======== encoder: 48 steps, 1 barrier each ========
    for (int t = 0; t < T_IN; t++) {
        const int p = t & 1, q = p ^ 1;
        if (gw < 600) {
            const int dir = gw / HD, j = gw % HD;
            const float* W = dir ? encWhh_b : encWhh_f;
            const float* bh = dir ? encbhh_b : encbhh_f;
            const float* h = g_h[p][dir];
            const float* gi = g_enc_gi[dir] + t * 900;
            float ar = 0.0f, az = 0.0f, an = 0.0f;
            for (int k = lane; k < HD; k += 32) {
                float hv = h[k];
                ar += W[j * HD + k] * hv;
                az += W[(HD + j) * HD + k] * hv;
                an += W[(2 * HD + j) * HD + k] * hv;
            }
            ar = wsum(ar); az = wsum(az); an = wsum(an);
            if (lane == 0) {
                float r = sigm(gi[j] + ar + bh[j]);
                float zg = sigm(gi[HD + j] + az + bh[HD + j]);
                float nn = tanhf(gi[2 * HD + j] + r * (an + bh[2 * HD + j]));
                float hn = (1.0f - zg) * nn + zg * h[j];
                g_h[q][dir][j] = hn;
                g_enc_out[t * HH + dir * HD + j] = hn;
            }
        }
        gbar(tgt);
    }

    // ======== VAE phase 1: mean, logv, z ========
    for (int task = gw; task < LL * ZZ; task += P_WARPS) {
        int l = task / ZZ, zi = task % ZZ;
        const float* eo = g_enc_out + l * HH;
        float am = 0.0f, av = 0.0f;
        for (int k = lane; k < HH; k += 32) {
            float e = eo[k];
            am += h2m_W[zi * HH + k] * e;
            av += h2v_W[zi * HH + k] * e;
        }
        am = wsum(am); av = wsum(av);
        if (lane == 0) {
            am += h2m_b[zi]; av += h2v_b[zi];
            out[OFF_MEAN + l * ZZ + zi] = am;
            out[OFF_LOGV + l * ZZ + zi] = av;
            g_z[l * ZZ + zi] = eps[l * ZZ + zi] * expf(0.5f * av) + am;
        }
    }
    gbar(tgt);

    // ======== VAE phase 2: latent_out = z @ l2h_W.T + b ========
    for (int task = gw; task < LL * HH; task += P_WARPS) {
        int l = task / HH, hh = task % HH;
        float a = 0.0f;
        for (int k = lane; k < ZZ; k += 32) a += l2h_W[hh * ZZ + k] * g_z[l * ZZ + k];
        a = wsum(a);
        if (lane == 0) g_lat[l * HH + hh] = a + l2h_b[hh];
    }
    gbar(tgt);

    // ======== VAE phase 3: M[l][e] = lat[l] . comb_W_app[e] ========
    for (int task = gw; task < LL * EE; task += P_WARPS) {
        int l = task / EE, e = task % EE;
        const float* lr = g_lat + l * HH;
        const float* wr = g_combW_app + e * HH;
        float a = 0.0f;
        for (int k = lane; k < HH; k += 32) a += lr[k] * wr[k];
        a = wsum(a);
        if (lane == 0) g_M[l * EE + e] = a;
    }
    gbar(tgt);

    // ======== decoder: 60 steps, 3 barriers each ========
    for (int t = 0; t < T_OUT; t++) {
        const int s = T_IN + t;
        const int p = s & 1, q = p ^ 1;
        const float* hF = g_h[p][0];
        const float* hB = g_h[p][1];

        // ---- DP1: attention scores + gh ----
        if (gw < 600) {
            const int dir = gw / HD, j = gw % HD;
            const float* W = dir ? decWhh_b : decWhh_f;
            const float* bh = dir ? decbhh_b : decbhh_f;
            const float* h = dir ? hB : hF;
            float ar = 0.0f, az = 0.0f, an = 0.0f;
            for (int k = lane; k < HD; k += 32) {
                float hv = h[k];
                ar += W[j * HD + k] * hv;
                az += W[(HD + j) * HD + k] * hv;
                an += W[(2 * HD + j) * HD + k] * hv;
            }
            ar = wsum(ar); az = wsum(az); an = wsum(an);
            if (lane == 0) {
                g_gh[dir][j] = ar + bh[j];
                g_gh[dir][HD + j] = az + bh[HD + j];
                g_gh[dir][2 * HD + j] = an + bh[2 * HD + j];
            }
        } else if (gw < 660) {
            const int l = gw - 600;
            const float* wr = attn_W + l * 900 + EE;
            float a = 0.0f;
            for (int k = lane; k < HH; k += 32) {
                float hv = (k < HD) ? hF[k] : hB[k - HD];
                a += wr[k] * hv;
            }
            a = wsum(a);
            if (lane == 0) g_s[l] = a + g_attn_x[t * LL + l];
        }
        gbar(tgt);

        // ---- DP2: softmax(s) -> aw; o = relu(comb_x + aw @ M) ----
        if (gw < 10) {
            float v0 = g_s[lane];
            float v1 = (lane + 32 < LL) ? g_s[lane + 32] : -1e30f;
            float m = wmax(fmaxf(v0, v1));
            float e0 = expf(v0 - m);
            float e1 = (lane + 32 < LL) ? expf(v1 - m) : 0.0f;
            float inv = 1.0f / wsum(e0 + e1);
            float aw0 = e0 * inv, aw1 = e1 * inv;
            int e = gw * 32 + lane;
            float acc = (e < EE) ? g_comb_x[t * EE + e] : 0.0f;
#pragma unroll
            for (int l = 0; l < LL; l++) {
                float a = (l < 32) ? __shfl_sync(0xffffffffu, aw0, l)
                                   : __shfl_sync(0xffffffffu, aw1, l - 32);
                if (e < EE) acc += a * g_M[l * EE + e];
            }
            if (e < EE) g_o[e] = fmaxf(acc, 0.0f);
        }
        gbar(tgt);

        // ---- DP3: gi = Wih@o, gates, new h, h_cat ----
        if (gw < 600) {
            const int dir = gw / HD, j = gw % HD;
            const float* W = dir ? decWih_b : decWih_f;
            const float* bi = dir ? decbih_b : decbih_f;
            float ar = 0.0f, az = 0.0f, an = 0.0f;
            for (int k = lane; k < EE; k += 32) {
                float ov = g_o[k];
                ar += W[j * EE + k] * ov;
                az += W[(EE + j) * EE + k] * ov;
                an += W[(2 * EE + j) * EE + k] * ov;
            }
            ar = wsum(ar); az = wsum(az); an = wsum(an);
            if (lane == 0) {
                const float* h = dir ? hB : hF;
                float r = sigm(ar + bi[j] + g_gh[dir][j]);
                float zg = sigm(az + bi[HD + j] + g_gh[dir][HD + j]);
                float nn = tanhf(an + bi[2 * HD + j] + r * g_gh[dir][2 * HD + j]);
                float hn = (1.0f - zg) * nn + zg * h[j];
                g_h[q][dir][j] = hn;
                g_hcat[t * HH + dir * HD + j] = hn;
            }
        }
        gbar(tgt);
    }
}

// ---------------- output GEMM ----------------
__global__ __launch_bounds__(512, 1) void out_gemm_kernel(
    const float* __restrict__ out_W, const float* __restrict__ out_b)
{
    extern __shared__ float sh[];  // 36000 floats = 144 KB
    for (int i = threadIdx.x; i < (T_OUT * HH) / 4; i += blockDim.x)
        ((float4*)sh)[i] = ((const float4*)g_hcat)[i];
    __syncthreads();

    int v = blockIdx.x * blockDim.x + threadIdx.x;
    if (v >= VV) return;
    float acc[T_OUT];
    float b = out_b[v];
#pragma unroll
    for (int t = 0; t < T_OUT; t++) acc[t] = b;

    const float4* wr = (const float4*)(out_W + (long)v * HH);
#pragma unroll 1
    for (int k4 = 0; k4 < HH / 4; k4++) {
        float4 w = wr[k4];
#pragma unroll
        for (int t = 0; t < T_OUT; t++) {
            float4 hv = *(const float4*)(sh + t * HH + k4 * 4);
            acc[t] = fmaf(w.x, hv.x, fmaf(w.y, hv.y, fmaf(w.z, hv.z, fmaf(w.w, hv.w, acc[t]))));
        }
    }
#pragma unroll
    for (int t = 0; t < T_OUT; t++) g_logits[(long)t * VV + v] = acc[t];
}

// ---------------- log_softmax per row ----------------
__global__ void lsm_kernel(float* __restrict__ out) {
    const int t = blockIdx.x;
    const float* row = g_logits + (long)t * VV;
    float* orow = out + (long)t * VV;
    __shared__ float sred[32];
    __shared__ float s_base;
    const int tid = threadIdx.x;
    const int nw = blockDim.x >> 5;

    float m = -3.4e38f;
    for (int v = tid; v < VV; v += blockDim.x) m = fmaxf(m, row[v]);
    m = wmax(m);
    if ((tid & 31) == 0) sred[tid >> 5] = m;
    __syncthreads();
    if (tid < 32) {
        float mm = (tid < nw) ? sred[tid] : -3.4e38f;
        mm = wmax(mm);
        if (tid == 0) sred[0] = mm;
    }
    __syncthreads();
    m = sred[0];
    __syncthreads();

    float ssum = 0.0f;
    for (int v = tid; v < VV; v += blockDim.x) ssum += expf(row[v] - m);
    ssum = wsum(ssum);
    if ((tid & 31) == 0) sred[tid >> 5] = ssum;
    __syncthreads();
    if (tid < 32) {
        float ss = (tid < nw) ? sred[tid] : 0.0f;
        ss = wsum(ss);
        if (tid == 0) s_base = m + logf(ss);
    }
    __syncthreads();
    float base = s_base;
    for (int v = tid; v < VV; v += blockDim.x) orow[v] = row[v] - base;
}

extern "C" void kernel_launch(void* const* d_in, const int* in_sizes, int n_in,
                              void* d_out, int out_size) {
    const int* input = (const int*)d_in[0];
    const int* target = (const int*)d_in[1];
    const float* eps = (const float*)d_in[2];
    const float* emb = (const float*)d_in[3];
    const float* encWih_f = (const float*)d_in[4];
    const float* encWhh_f = (const float*)d_in[5];
    const float* encbih_f = (const float*)d_in[6];
    const float* encbhh_f = (const float*)d_in[7];
    const float* encWih_b = (const float*)d_in[8];
    const float* encWhh_b = (const float*)d_in[9];
    const float* encbih_b = (const float*)d_in[10];
    const float* encbhh_b = (const float*)d_in[11];
    const float* decWih_f = (const float*)d_in[12];
    const float* decWhh_f = (const float*)d_in[13];
    const float* decbih_f = (const float*)d_in[14];
    const float* decbhh_f = (const float*)d_in[15];
    const float* decWih_b = (const float*)d_in[16];
    const float* decWhh_b = (const float*)d_in[17];
    const float* decbih_b = (const float*)d_in[18];
    const float* decbhh_b = (const float*)d_in[19];
    const float* h2m_W = (const float*)d_in[20];
    const float* h2m_b = (const float*)d_in[21];
    const float* h2v_W = (const float*)d_in[22];
    const float* h2v_b = (const float*)d_in[23];
    const float* l2h_W = (const float*)d_in[24];
    const float* l2h_b = (const float*)d_in[25];
    const float* attn_W = (const float*)d_in[26];
    const float* attn_b = (const float*)d_in[27];
    const float* comb_W = (const float*)d_in[28];
    const float* comb_b = (const float*)d_in[29];
    const float* out_W = (const float*)d_in[30];
    const float* out_b = (const float*)d_in[31];
    float* out = (float*)d_out;

    cudaFuncSetAttribute(out_gemm_kernel, cudaFuncAttributeMaxDynamicSharedMemorySize,
                         T_OUT * HH * sizeof(float));

    init_kernel<<<1, 256>>>();
    copy_combW_kernel<<<(EE * HH + 255) / 256, 256>>>(comb_W);
    prepass_kernel<<<N_TASKS / 8, 256>>>(input, target, emb,
                                         encWih_f, encbih_f, encWih_b, encbih_b,
                                         attn_W, attn_b, comb_W, comb_b);
    seq_kernel<<<P_CTAS, P_THREADS>>>(eps,
                                      encWhh_f, encbhh_f, encWhh_b, encbhh_b,
                                      decWih_f, decWhh_f, decbih_f, decbhh_f,
                                      decWih_b, decWhh_b, decbih_b, decbhh_b,
                                      h2m_W, h2m_b, h2v_W, h2v_b, l2h_W, l2h_b,
                                      attn_W, out);
    out_gemm_kernel<<<(VV + 511) / 512, 512, T_OUT * HH * sizeof(float)>>>(out_W, out_b);
    lsm_kernel<<<T_OUT, 1024>>>(out);
}

// round 2
// speedup vs baseline: 1.1500x; 1.1500x over previous
#include <cuda_runtime.h>
#include <math.h>

#define VV 50257
#define EE 300
#define HH 600
#define HD 300
#define LL 60
#define ZZ 100
#define T_IN 48
#define T_OUT 60
#define EOS_TOK 1

#define OFF_MEAN (T_OUT * VV)
#define OFF_LOGV (OFF_MEAN + LL * ZZ)

#define P_CTAS 42
#define P_THREADS 512
#define P_NWARP (P_THREADS / 32)
#define P_WARPS (P_CTAS * P_NWARP)

// smem layout (floats): M[18000] | h[608] | o[320] | aw[64]
#define SM_M 0
#define SM_H 18000
#define SM_O 18608
#define SM_AW 18928
#define SEQ_SMEM_FLOATS (18928 + 64)
#define SEQ_SMEM_BYTES (SEQ_SMEM_FLOATS * 4)

// ---------------- device scratch ----------------
__device__ float g_h[2][2][HD];
__device__ float g_enc_gi[2][T_IN * 900];
__device__ float g_enc_out[LL * HH];
__device__ float g_z[LL * ZZ];
__device__ float g_lat[LL * HH];
__device__ float g_M[LL * EE];
__device__ float g_combW_app[EE * HH];
__device__ float g_attn_x[T_OUT * LL];
__device__ float g_comb_x[T_OUT * EE];
__device__ float g_s[LL];
__device__ float g_hcat[T_OUT * HH];
__device__ float g_logits[T_OUT * VV];
__device__ unsigned g_bar;

// ---------------- helpers ----------------
__device__ __forceinline__ float wsum(float v) {
#pragma unroll
    for (int o = 16; o; o >>= 1) v += __shfl_xor_sync(0xffffffffu, v, o);
    return v;
}
__device__ __forceinline__ float wmax(float v) {
#pragma unroll
    for (int o = 16; o; o >>= 1) v = fmaxf(v, __shfl_xor_sync(0xffffffffu, v, o));
    return v;
}
__device__ __forceinline__ float sigm(float x) { return 1.0f / (1.0f + expf(-x)); }

// grid barrier: single red.release arrive + ld.acquire spin (no RMW polling,
// no fence -> no CCTL.IVALL -> L1-cached weights survive).
__device__ __forceinline__ void gbar(unsigned& tgt) {
    __syncthreads();
    tgt += P_CTAS;
    if (threadIdx.x == 0) {
        unsigned* bp = &g_bar;
        asm volatile("red.release.gpu.add.u32 [%0], 1;" :: "l"(bp) : "memory");
        unsigned v;
        do {
            asm volatile("ld.acquire.gpu.u32 %0, [%1];" : "=r"(v) : "l"(bp) : "memory");
        } while (v < tgt);
    }
    __syncthreads();
}

// ---------------- init ----------------
__global__ void init_kernel() {
    int tid = threadIdx.x;
    if (tid == 0) g_bar = 0u;
    for (int i = tid; i < 2 * 2 * HD; i += blockDim.x) (&g_h[0][0][0])[i] = 0.0f;
    for (int i = tid; i < (LL - T_IN) * HH; i += blockDim.x) g_enc_out[T_IN * HH + i] = 0.0f;
}

__global__ void copy_combW_kernel(const float* __restrict__ comb_W) {
    int i = blockIdx.x * blockDim.x + threadIdx.x;
    if (i < EE * HH) {
        int e = i / HH, h = i % HH;
        g_combW_app[i] = comb_W[e * 900 + EE + h];
    }
}

// ---------------- prepass: warp-per-row, loop over t (weights in regs) ----------------
#define PP_WARPS 2160
__global__ void prepass_kernel(
    const int* __restrict__ input, const int* __restrict__ target,
    const float* __restrict__ emb,
    const float* __restrict__ encWih_f, const float* __restrict__ encbih_f,
    const float* __restrict__ encWih_b, const float* __restrict__ encbih_b,
    const float* __restrict__ attn_W, const float* __restrict__ attn_b,
    const float* __restrict__ comb_W, const float* __restrict__ comb_b)
{
    int gw = blockIdx.x * 8 + (threadIdx.x >> 5);
    int lane = threadIdx.x & 31;
    if (gw >= PP_WARPS) return;

    if (gw < 1800) {                       // enc gi rows: (dir, row)
        int dir = gw / 900, row = gw % 900;
        const float* W = dir ? encWih_b : encWih_f;
        float bi = (dir ? encbih_b : encbih_f)[row];
        float wr[10];
#pragma unroll
        for (int i = 0; i < 10; i++) {
            int k = lane + 32 * i;
            wr[i] = (k < EE) ? W[row * EE + k] : 0.0f;
        }
        for (int t = 0; t < T_IN; t++) {
            const float* x = emb + (long)input[t] * EE;
            float a = 0.0f;
#pragma unroll
            for (int i = 0; i < 10; i++) {
                int k = lane + 32 * i;
                if (k < EE) a = fmaf(wr[i], x[k], a);
            }
            a = wsum(a);
            if (lane == 0) g_enc_gi[dir][t * 900 + row] = a + bi;
        }
    } else if (gw < 1860) {                // attn x-part rows: l
        int l = gw - 1800;
        float bi = attn_b[l];
        float wr[10];
#pragma unroll
        for (int i = 0; i < 10; i++) {
            int k = lane + 32 * i;
            wr[i] = (k < EE) ? attn_W[l * 900 + k] : 0.0f;
        }
        for (int t = 0; t < T_OUT; t++) {
            int tok = (t == 0) ? EOS_TOK : target[t - 1];
            const float* x = emb + (long)tok * EE;
            float a = 0.0f;
#pragma unroll
            for (int i = 0; i < 10; i++) {
                int k = lane + 32 * i;
                if (k < EE) a = fmaf(wr[i], x[k], a);
            }
            a = wsum(a);
            if (lane == 0) g_attn_x[t * LL + l] = a + bi;
        }
    } else {                               // comb x-part rows: e
        int e = gw - 1860;
        float bi = comb_b[e];
        float wr[10];
#pragma unroll
        for (int i = 0; i < 10; i++) {
            int k = lane + 32 * i;
            wr[i] = (k < EE) ? comb_W[e * 900 + k] : 0.0f;
        }
        for (int t = 0; t < T_OUT; t++) {
            int tok = (t == 0) ? EOS_TOK : target[t - 1];
            const float* x = emb + (long)tok * EE;
            float a = 0.0f;
#pragma unroll
            for (int i = 0; i < 10; i++) {
                int k = lane + 32 * i;
                if (k < EE) a = fmaf(wr[i], x[k], a);
            }
            a = wsum(a);
            if (lane == 0) g_comb_x[t * EE + e] = a + bi;
        }
    }
}

// ---------------- persistent sequential kernel ----------------
__global__ __launch_bounds__(P_THREADS, 1) void seq_kernel(
    const float* __restrict__ eps,
    const float* __restrict__ encWhh_f, const float* __restrict__ encbhh_f,
    const float* __restrict__ encWhh_b, const float* __restrict__ encbhh_b,
    const float* __restrict__ decWih_f, const float* __restrict__ decWhh_f,
    const float* __restrict__ decbih_f, const float* __restrict__ decbhh_f,
    const float* __restrict__ decWih_b, const float* __restrict__ decWhh_b,
    const float* __restrict__ decbih_b, const float* __restrict__ decbhh_b,
    const float* __restrict__ h2m_W, const float* __restrict__ h2m_b,
    const float* __restrict__ h2v_W, const float* __restrict__ h2v_b,
    const float* __restrict__ l2h_W, const float* __restrict__ l2h_b,
    const float* __restrict__ attn_W,
    float* __restrict__ out)
{
    extern __shared__ float sm[];
    float* s_M = sm + SM_M;
    float* s_h = sm + SM_H;
    float* s_o = sm + SM_O;
    float* s_aw = sm + SM_AW;

    const int tid = threadIdx.x;
    const int lane = tid & 31;
    const int gw = blockIdx.x * P_NWARP + (tid >> 5);
    unsigned tgt = 0;
    float* hbuf = (float*)g_h;   // [2][2][300] flat

    int dir = 0, j = 0;
    float wA[30];   // enc Whh rows -> later dec Whh rows
    float wB[30];   // dec Wih rows (or attn row for attn warps)
    float ebr = 0, ebz = 0, ebn = 0;

    if (gw < 600) {
        dir = gw / HD; j = gw % HD;
        const float* W = dir ? encWhh_b : encWhh_f;
        const float* bh = dir ? encbhh_b : encbhh_f;
#pragma unroll
        for (int i = 0; i < 10; i++) {
            int k = lane + 32 * i;
            bool ok = k < HD;
            wA[i]      = ok ? W[j * HD + k] : 0.0f;
            wA[10 + i] = ok ? W[(HD + j) * HD + k] : 0.0f;
            wA[20 + i] = ok ? W[(2 * HD + j) * HD + k] : 0.0f;
        }
        ebr = bh[j]; ebz = bh[HD + j]; ebn = bh[2 * HD + j];
    }

    // ======== encoder: 48 steps, 1 barrier each ========
    for (int t = 0; t < T_IN; t++) {
        const int p = t & 1, q = p ^ 1;
        for (int i = tid; i < HH; i += P_THREADS) s_h[i] = __ldcg(hbuf + p * HH + i);
        __syncthreads();
        if (gw < 600) {
            const float* hs = s_h + dir * HD;
            float ar = 0, az = 0, an = 0;
#pragma unroll
            for (int i = 0; i < 10; i++) {
                int k = lane + 32 * i;
                if (k < HD) {
                    float hv = hs[k];
                    ar = fmaf(wA[i], hv, ar);
                    az = fmaf(wA[10 + i], hv, az);
                    an = fmaf(wA[20 + i], hv, an);
                }
            }
            ar = wsum(ar); az = wsum(az); an = wsum(an);
            if (lane == 0) {
                const float* gi = g_enc_gi[dir] + t * 900;
                float r = sigm(gi[j] + ar + ebr);
                float zg = sigm(gi[HD + j] + az + ebz);
                float nn = tanhf(gi[2 * HD + j] + r * (an + ebn));
                float hn = (1.0f - zg) * nn + zg * hs[j];
                hbuf[q * HH + dir * HD + j] = hn;
                g_enc_out[t * HH + dir * HD + j] = hn;
            }
        }
        gbar(tgt);
    }

    // ---- preload decoder weights (overlaps with VAE work below) ----
    float dbhr = 0, dbhz = 0, dbhn = 0, dbir = 0, dbiz = 0, dbin = 0;
    if (gw < 600) {
        const float* Wh = dir ? decWhh_b : decWhh_f;
        const float* Wi = dir ? decWih_b : decWih_f;
#pragma unroll
        for (int i = 0; i < 10; i++) {
            int k = lane + 32 * i;
            bool ok = k < HD;
            wA[i]      = ok ? Wh[j * HD + k] : 0.0f;
            wA[10 + i] = ok ? Wh[(HD + j) * HD + k] : 0.0f;
            wA[20 + i] = ok ? Wh[(2 * HD + j) * HD + k] : 0.0f;
            wB[i]      = ok ? Wi[j * EE + k] : 0.0f;
            wB[10 + i] = ok ? Wi[(EE + j) * EE + k] : 0.0f;
            wB[20 + i] = ok ? Wi[(2 * EE + j) * EE + k] : 0.0f;
        }
        const float* bh = dir ? decbhh_b : decbhh_f;
        const float* bi = dir ? decbih_b : decbih_f;
        dbhr = bh[j]; dbhz = bh[HD + j]; dbhn = bh[2 * HD + j];
        dbir = bi[j]; dbiz = bi[HD + j]; dbin = bi[2 * HD + j];
    } else if (gw < 660) {
        int l = gw - 600;
#pragma unroll
        for (int i = 0; i < 19; i++) {
            int k = lane + 32 * i;
            wB[i] = (k < HH) ? attn_W[l * 900 + EE + k] : 0.0f;
        }
    }

    // ======== VAE phase 1: mean, logv, z ========
    for (int task = gw; task < LL * ZZ; task += P_WARPS) {
        int l = task / ZZ, zi = task % ZZ;
        float am = 0, av = 0;
        for (int k = lane; k < HH; k += 32) {
            float e = __ldcg(g_enc_out + l * HH + k);
            am = fmaf(h2m_W[zi * HH + k], e, am);
            av = fmaf(h2v_W[zi * HH + k], e, av);
        }
        am = wsum(am); av = wsum(av);
        if (lane == 0) {
            am += h2m_b[zi]; av += h2v_b[zi];
            out[OFF_MEAN + l * ZZ + zi] = am;
            out[OFF_LOGV + l * ZZ + zi] = av;
            g_z[l * ZZ + zi] = eps[l * ZZ + zi] * expf(0.5f * av) + am;
        }
    }
    gbar(tgt);

    // ======== VAE phase 2: latent_out ========
    for (int task = gw; task < LL * HH; task += P_WARPS) {
        int l = task / HH, hh = task % HH;
        float a = 0;
        for (int k = lane; k < ZZ; k += 32)
            a = fmaf(l2h_W[hh * ZZ + k], __ldcg(g_z + l * ZZ + k), a);
        a = wsum(a);
        if (lane == 0) g_lat[l * HH + hh] = a + l2h_b[hh];
    }
    gbar(tgt);

    // ======== VAE phase 3: M = lat @ combW_app^T ========
    for (int task = gw; task < LL * EE; task += P_WARPS) {
        int l = task / EE, e = task % EE;
        float a = 0;
        for (int k = lane; k < HH; k += 32)
            a = fmaf(__ldcg(g_lat + l * HH + k), g_combW_app[e * HH + k], a);
        a = wsum(a);
        if (lane == 0) g_M[l * EE + e] = a;
    }
    gbar(tgt);

    // ---- stage M into SMEM once (reused all 60 decoder steps) ----
    for (int i = tid; i < LL * EE; i += P_THREADS) s_M[i] = __ldcg(g_M + i);

    // ======== decoder: 60 steps, 2 barriers each ========
    for (int t = 0; t < T_OUT; t++) {
        const int p = t & 1, q = p ^ 1;
        for (int i = tid; i < HH; i += P_THREADS) s_h[i] = __ldcg(hbuf + p * HH + i);
        __syncthreads();

        // ---- phase A: gh (kept in regs) + attention scores ----
        float ghr = 0, ghz = 0, ghn = 0;
        if (gw < 600) {
            const float* hs = s_h + dir * HD;
            float ar = 0, az = 0, an = 0;
#pragma unroll
            for (int i = 0; i < 10; i++) {
                int k = lane + 32 * i;
                if (k < HD) {
                    float hv = hs[k];
                    ar = fmaf(wA[i], hv, ar);
                    az = fmaf(wA[10 + i], hv, az);
                    an = fmaf(wA[20 + i], hv, an);
                }
            }
            ar = wsum(ar); az = wsum(az); an = wsum(an);
            ghr = ar + dbhr; ghz = az + dbhz; ghn = an + dbhn;
        } else if (gw < 660) {
            int l = gw - 600;
            float a = 0;
#pragma unroll
            for (int i = 0; i < 19; i++) {
                int k = lane + 32 * i;
                if (k < HH) a = fmaf(wB[i], s_h[k], a);
            }
            a = wsum(a);
            if (lane == 0) g_s[l] = a + g_attn_x[t * LL + l];
        }
        gbar(tgt);

        // ---- phase B: per-CTA softmax + o, then gates ----
        if (tid < 32) {
            float v0 = __ldcg(g_s + lane);
            float v1 = (lane + 32 < LL) ? __ldcg(g_s + lane + 32) : -1e30f;
            float m = wmax(fmaxf(v0, v1));
            float e0 = expf(v0 - m);
            float e1 = (lane + 32 < LL) ? expf(v1 - m) : 0.0f;
            float inv = 1.0f / wsum(e0 + e1);
            s_aw[lane] = e0 * inv;
            if (lane + 32 < LL) s_aw[lane + 32] = e1 * inv;
        }
        __syncthreads();
        if (tid < EE) {
            float acc = g_comb_x[t * EE + tid];
#pragma unroll
            for (int l = 0; l < LL; l++) acc = fmaf(s_aw[l], s_M[l * EE + tid], acc);
            s_o[tid] = fmaxf(acc, 0.0f);
        }
        __syncthreads();
        if (gw < 600) {
            float ar = 0, az = 0, an = 0;
#pragma unroll
            for (int i = 0; i < 10; i++) {
                int k = lane + 32 * i;
                if (k < EE) {
                    float ov = s_o[k];
                    ar = fmaf(wB[i], ov, ar);
                    az = fmaf(wB[10 + i], ov, az);
                    an = fmaf(wB[20 + i], ov, an);
                }
            }
            ar = wsum(ar); az = wsum(az); an = wsum(an);
            if (lane == 0) {
                float r = sigm(ar + dbir + ghr);
                float zg = sigm(az + dbiz + ghz);
                float nn = tanhf(an + dbin + r * ghn);
                float hn = (1.0f - zg) * nn + zg * s_h[dir * HD + j];
                hbuf[q * HH + dir * HD + j] = hn;
                g_hcat[t * HH + dir * HD + j] = hn;
            }
        }
        gbar(tgt);
    }
}

// ---------------- output GEMM: 394 CTAs (197 v-blocks x 2 t-halves) ----------------
#define OG_TH 30
__global__ __launch_bounds__(256) void out_gemm_kernel(
    const float* __restrict__ out_W, const float* __restrict__ out_b)
{
    int vb = blockIdx.x >> 1;
    int th = blockIdx.x & 1;
    int v = vb * 256 + threadIdx.x;
    if (v >= VV) return;

    float acc[OG_TH];
    float b = out_b[v];
#pragma unroll
    for (int tt = 0; tt < OG_TH; tt++) acc[tt] = b;

    const float4* wr = (const float4*)(out_W + (long)v * HH);
    const float4* hc = (const float4*)(g_hcat + th * OG_TH * HH);
#pragma unroll 1
    for (int k4 = 0; k4 < HH / 4; k4++) {
        float4 w = wr[k4];
#pragma unroll
        for (int tt = 0; tt < OG_TH; tt++) {
            float4 hv = hc[tt * (HH / 4) + k4];
            acc[tt] = fmaf(w.x, hv.x, fmaf(w.y, hv.y, fmaf(w.z, hv.z, fmaf(w.w, hv.w, acc[tt]))));
        }
    }
#pragma unroll
    for (int tt = 0; tt < OG_TH; tt++)
        g_logits[(long)(th * OG_TH + tt) * VV + v] = acc[tt];
}

// ---------------- log_softmax per row ----------------
__global__ void lsm_kernel(float* __restrict__ out) {
    const int t = blockIdx.x;
    const float* row = g_logits + (long)t * VV;
    float* orow = out + (long)t * VV;
    __shared__ float sred[32];
    __shared__ float s_base;
    const int tid = threadIdx.x;
    const int nw = blockDim.x >> 5;

    float m = -3.4e38f;
    for (int v = tid; v < VV; v += blockDim.x) m = fmaxf(m, row[v]);
    m = wmax(m);
    if ((tid & 31) == 0) sred[tid >> 5] = m;
    __syncthreads();
    if (tid < 32) {
        float mm = (tid < nw) ? sred[tid] : -3.4e38f;
        mm = wmax(mm);
        if (tid == 0) sred[0] = mm;
    }
    __syncthreads();
    m = sred[0];
    __syncthreads();

    float ssum = 0.0f;
    for (int v = tid; v < VV; v += blockDim.x) ssum += expf(row[v] - m);
    ssum = wsum(ssum);
    if ((tid & 31) == 0) sred[tid >> 5] = ssum;
    __syncthreads();
    if (tid < 32) {
        float ss = (tid < nw) ? sred[tid] : 0.0f;
        ss = wsum(ss);
        if (tid == 0) s_base = m + logf(ss);
    }
    __syncthreads();
    float base = s_base;
    for (int v = tid; v < VV; v += blockDim.x) orow[v] = row[v] - base;
}

extern "C" void kernel_launch(void* const* d_in, const int* in_sizes, int n_in,
                              void* d_out, int out_size) {
    const int* input = (const int*)d_in[0];
    const int* target = (const int*)d_in[1];
    const float* eps = (const float*)d_in[2];
    const float* emb = (const float*)d_in[3];
    const float* encWih_f = (const float*)d_in[4];
    const float* encWhh_f = (const float*)d_in[5];
    const float* encbih_f = (const float*)d_in[6];
    const float* encbhh_f = (const float*)d_in[7];
    const float* encWih_b = (const float*)d_in[8];
    const float* encWhh_b = (const float*)d_in[9];
    const float* encbih_b = (const float*)d_in[10];
    const float* encbhh_b = (const float*)d_in[11];
    const float* decWih_f = (const float*)d_in[12];
    const float* decWhh_f = (const float*)d_in[13];
    const float* decbih_f = (const float*)d_in[14];
    const float* decbhh_f = (const float*)d_in[15];
    const float* decWih_b = (const float*)d_in[16];
    const float* decWhh_b = (const float*)d_in[17];
    const float* decbih_b = (const float*)d_in[18];
    const float* decbhh_b = (const float*)d_in[19];
    const float* h2m_W = (const float*)d_in[20];
    const float* h2m_b = (const float*)d_in[21];
    const float* h2v_W = (const float*)d_in[22];
    const float* h2v_b = (const float*)d_in[23];
    const float* l2h_W = (const float*)d_in[24];
    const float* l2h_b = (const float*)d_in[25];
    const float* attn_W = (const float*)d_in[26];
    const float* attn_b = (const float*)d_in[27];
    const float* comb_W = (const float*)d_in[28];
    const float* comb_b = (const float*)d_in[29];
    const float* out_W = (const float*)d_in[30];
    const float* out_b = (const float*)d_in[31];
    float* out = (float*)d_out;

    cudaFuncSetAttribute(seq_kernel, cudaFuncAttributeMaxDynamicSharedMemorySize,
                         SEQ_SMEM_BYTES);

    init_kernel<<<1, 256>>>();
    copy_combW_kernel<<<(EE * HH + 255) / 256, 256>>>(comb_W);
    prepass_kernel<<<(PP_WARPS + 7) / 8, 256>>>(input, target, emb,
                                                encWih_f, encbih_f, encWih_b, encbih_b,
                                                attn_W, attn_b, comb_W, comb_b);
    seq_kernel<<<P_CTAS, P_THREADS, SEQ_SMEM_BYTES>>>(eps,
                                      encWhh_f, encbhh_f, encWhh_b, encbhh_b,
                                      decWih_f, decWhh_f, decbih_f, decbhh_f,
                                      decWih_b, decWhh_b, decbih_b, decbhh_b,
                                      h2m_W, h2m_b, h2v_W, h2v_b, l2h_W, l2h_b,
                                      attn_W, out);
    out_gemm_kernel<<<((VV + 255) / 256) * 2, 256>>>(out_W, out_b);
    lsm_kernel<<<T_OUT, 1024>>>(out);
}

// round 5
// speedup vs baseline: 1.4163x; 1.2316x over previous
#include <cuda_runtime.h>
#include <math.h>

#define VV 50257
#define EE 300
#define HH 600
#define HD 300
#define LL 60
#define ZZ 100
#define T_IN 48
#define T_OUT 60
#define EOS_TOK 1

#define OFF_MEAN (T_OUT * VV)
#define OFF_LOGV (OFF_MEAN + LL * ZZ)

#define P_CTAS 40
#define P_THREADS 512
#define P_NWARP 16
#define P_WARPS (P_CTAS * P_NWARP)

// smem layout (floats)
#define SM_M 0          // 18000
#define SM_H 18000      // 600
#define SM_O 18600      // 304
#define SM_AW 18904     // 64
#define SM_S 18968      // 64
#define SEQ_SMEM_FLOATS 19032
#define SEQ_SMEM_BYTES (SEQ_SMEM_FLOATS * 4)

// ---------------- device scratch ----------------
__device__ float g_h[2][2][HD];
__device__ float g_enc_gi[2][T_IN * 900];
__device__ float g_enc_out[LL * HH];
__device__ float g_z[LL * ZZ];
__device__ float g_M[LL * EE];
__device__ float g_C[EE * ZZ];         // combW_app . l2h_W
__device__ float g_d[EE];              // combW_app . l2h_b
__device__ float g_l2hT[ZZ * HH];
__device__ float g_attn_x[T_OUT * LL];
__device__ float g_comb_x[T_OUT * EE];
__device__ float g_hT[HH * 64];        // transposed hcat, t padded to 64
__device__ float g_logits[T_OUT * VV];
__device__ unsigned g_bar;
__device__ unsigned g_barE[2];

// ---------------- helpers ----------------
__device__ __forceinline__ float wsum(float v) {
#pragma unroll
    for (int o = 16; o; o >>= 1) v += __shfl_xor_sync(0xffffffffu, v, o);
    return v;
}
__device__ __forceinline__ float wmax(float v) {
#pragma unroll
    for (int o = 16; o; o >>= 1) v = fmaxf(v, __shfl_xor_sync(0xffffffffu, v, o));
    return v;
}
__device__ __forceinline__ float sigm(float x) { return 1.0f / (1.0f + expf(-x)); }

__device__ __forceinline__ void gbar_n(unsigned* ctr, int n, unsigned& tgt) {
    __syncthreads();
    tgt += n;
    if (threadIdx.x == 0) {
        asm volatile("red.release.gpu.add.u32 [%0], 1;" :: "l"(ctr) : "memory");
        unsigned v;
        do {
            asm volatile("ld.acquire.gpu.u32 %0, [%1];" : "=r"(v) : "l"(ctr) : "memory");
        } while (v < tgt);
    }
    __syncthreads();
}

// packed f32x2 helpers
__device__ __forceinline__ unsigned long long packf2(float lo, float hi) {
    unsigned long long r;
    asm("mov.b64 %0, {%1, %2};" : "=l"(r) : "f"(lo), "f"(hi));
    return r;
}
__device__ __forceinline__ void ffma2(unsigned long long& d, unsigned long long a, unsigned long long b) {
    asm("fma.rn.f32x2 %0, %1, %2, %0;" : "+l"(d) : "l"(a), "l"(b));
}
__device__ __forceinline__ float2 unpackf2(unsigned long long v) {
    float lo, hi;
    asm("mov.b64 {%0, %1}, %2;" : "=f"(lo), "=f"(hi) : "l"(v));
    return make_float2(lo, hi);
}

// ---------------- init ----------------
__global__ void init_kernel() {
    int tid = threadIdx.x;
    if (tid == 0) { g_bar = 0u; g_barE[0] = 0u; g_barE[1] = 0u; }
    for (int i = tid; i < 2 * 2 * HD; i += blockDim.x) (&g_h[0][0][0])[i] = 0.0f;
    for (int i = tid; i < (LL - T_IN) * HH; i += blockDim.x) g_enc_out[T_IN * HH + i] = 0.0f;
}

// ---------------- l2h transpose ----------------
__global__ void transpose_l2h(const float* __restrict__ l2h_W) {
    int i = blockIdx.x * 256 + threadIdx.x;
    if (i < ZZ * HH) {
        int h = i / ZZ, k = i % ZZ;
        g_l2hT[k * HH + h] = l2h_W[i];
    }
}

// ---------------- prep C, d (input-only folding) ----------------
#define PC_TASKS 30300
__global__ void prepC_kernel(const float* __restrict__ comb_W, const float* __restrict__ l2h_b) {
    int gw = blockIdx.x * 8 + (threadIdx.x >> 5);
    int lane = threadIdx.x & 31;
    if (gw >= PC_TASKS) return;
    if (gw < 30000) {
        int e = gw / ZZ, k = gw % ZZ;
        const float* cw = comb_W + e * 900 + EE;
        const float* lt = g_l2hT + k * HH;
        float a = 0.0f;
        for (int h = lane; h < HH; h += 32) a = fmaf(cw[h], lt[h], a);
        a = wsum(a);
        if (lane == 0) g_C[e * ZZ + k] = a;
    } else {
        int e = gw - 30000;
        const float* cw = comb_W + e * 900 + EE;
        float a = 0.0f;
        for (int h = lane; h < HH; h += 32) a = fmaf(cw[h], l2h_b[h], a);
        a = wsum(a);
        if (lane == 0) g_d[e] = a;
    }
}

// ---------------- prepass: warp-per-row, loop over t ----------------
#define PP_WARPS 2160
__global__ void prepass_kernel(
    const int* __restrict__ input, const int* __restrict__ target,
    const float* __restrict__ emb,
    const float* __restrict__ encWih_f, const float* __restrict__ encbih_f,
    const float* __restrict__ encWih_b, const float* __restrict__ encbih_b,
    const float* __restrict__ attn_W, const float* __restrict__ attn_b,
    const float* __restrict__ comb_W, const float* __restrict__ comb_b)
{
    int gw = blockIdx.x * 8 + (threadIdx.x >> 5);
    int lane = threadIdx.x & 31;
    if (gw >= PP_WARPS) return;

    if (gw < 1800) {
        int dir = gw / 900, row = gw % 900;
        const float* W = dir ? encWih_b : encWih_f;
        float bi = (dir ? encbih_b : encbih_f)[row];
        float wr[10];
#pragma unroll
        for (int i = 0; i < 10; i++) {
            int k = lane + 32 * i;
            wr[i] = (k < EE) ? W[row * EE + k] : 0.0f;
        }
        for (int t = 0; t < T_IN; t++) {
            const float* x = emb + (long)input[t] * EE;
            float a = 0.0f;
#pragma unroll
            for (int i = 0; i < 10; i++) {
                int k = lane + 32 * i;
                if (k < EE) a = fmaf(wr[i], x[k], a);
            }
            a = wsum(a);
            if (lane == 0) g_enc_gi[dir][t * 900 + row] = a + bi;
        }
    } else if (gw < 1860) {
        int l = gw - 1800;
        float bi = attn_b[l];
        float wr[10];
#pragma unroll
        for (int i = 0; i < 10; i++) {
            int k = lane + 32 * i;
            wr[i] = (k < EE) ? attn_W[l * 900 + k] : 0.0f;
        }
        for (int t = 0; t < T_OUT; t++) {
            int tok = (t == 0) ? EOS_TOK : target[t - 1];
            const float* x = emb + (long)tok * EE;
            float a = 0.0f;
#pragma unroll
            for (int i = 0; i < 10; i++) {
                int k = lane + 32 * i;
                if (k < EE) a = fmaf(wr[i], x[k], a);
            }
            a = wsum(a);
            if (lane == 0) g_attn_x[t * LL + l] = a + bi;
        }
    } else {
        int e = gw - 1860;
        float bi = comb_b[e];
        float wr[10];
#pragma unroll
        for (int i = 0; i < 10; i++) {
            int k = lane + 32 * i;
            wr[i] = (k < EE) ? comb_W[e * 900 + k] : 0.0f;
        }
        for (int t = 0; t < T_OUT; t++) {
            int tok = (t == 0) ? EOS_TOK : target[t - 1];
            const float* x = emb + (long)tok * EE;
            float a = 0.0f;
#pragma unroll
            for (int i = 0; i < 10; i++) {
                int k = lane + 32 * i;
                if (k < EE) a = fmaf(wr[i], x[k], a);
            }
            a = wsum(a);
            if (lane == 0) g_comb_x[t * EE + e] = a + bi;
        }
    }
}

// ---------------- persistent sequential kernel ----------------
__global__ __launch_bounds__(P_THREADS, 1) void seq_kernel(
    const float* __restrict__ eps,
    const float* __restrict__ encWhh_f, const float* __restrict__ encbhh_f,
    const float* __restrict__ encWhh_b, const float* __restrict__ encbhh_b,
    const float* __restrict__ decWih_f, const float* __restrict__ decWhh_f,
    const float* __restrict__ decbih_f, const float* __restrict__ decbhh_f,
    const float* __restrict__ decWih_b, const float* __restrict__ decWhh_b,
    const float* __restrict__ decbih_b, const float* __restrict__ decbhh_b,
    const float* __restrict__ h2m_W, const float* __restrict__ h2m_b,
    const float* __restrict__ h2v_W, const float* __restrict__ h2v_b,
    const float* __restrict__ attn_W,
    float* __restrict__ out)
{
    extern __shared__ float sm[];
    float* s_M = sm + SM_M;
    float* s_h = sm + SM_H;
    float* s_o = sm + SM_O;
    float* s_aw = sm + SM_AW;
    float* s_s = sm + SM_S;

    const int tid = threadIdx.x;
    const int lane = tid & 31;
    const int warp = tid >> 5;
    const int gw = blockIdx.x * P_NWARP + warp;
    const int grp = blockIdx.x / 20;          // encoder direction group
    unsigned tgt = 0, tgtE = 0;
    float* hbuf = (float*)g_h;

    const bool isGate = (warp >= 1);          // warps 1..15 own gate rows
    int gr = blockIdx.x * 15 + (warp - 1);    // global row [0,600)
    int dir = 0, j = 0;
    if (isGate) { dir = gr / HD; j = gr % HD; }

    float wA[30], wB[30];
    float ebr = 0, ebz = 0, ebn = 0;

    if (isGate) {
        const float* W = dir ? encWhh_b : encWhh_f;
        const float* bh = dir ? encbhh_b : encbhh_f;
#pragma unroll
        for (int i = 0; i < 10; i++) {
            int k = lane + 32 * i;
            bool ok = k < HD;
            wA[i]      = ok ? W[j * HD + k] : 0.0f;
            wA[10 + i] = ok ? W[(HD + j) * HD + k] : 0.0f;
            wA[20 + i] = ok ? W[(2 * HD + j) * HD + k] : 0.0f;
        }
        ebr = bh[j]; ebz = bh[HD + j]; ebn = bh[2 * HD + j];
    }

    // ======== encoder: 48 steps, split-group barriers ========
    for (int t = 0; t < T_IN; t++) {
        const int p = t & 1, q = p ^ 1;
        if (tid < HD) s_h[tid] = __ldcg(&hbuf[p * HH + grp * HD + tid]);
        __syncthreads();
        if (isGate) {
            float ar = 0, az = 0, an = 0;
#pragma unroll
            for (int i = 0; i < 10; i++) {
                int k = lane + 32 * i;
                if (k < HD) {
                    float hv = s_h[k];
                    ar = fmaf(wA[i], hv, ar);
                    az = fmaf(wA[10 + i], hv, az);
                    an = fmaf(wA[20 + i], hv, an);
                }
            }
            ar = wsum(ar); az = wsum(az); an = wsum(an);
            if (lane == 0) {
                const float* gi = g_enc_gi[grp] + t * 900;
                float r = sigm(gi[j] + ar + ebr);
                float zg = sigm(gi[HD + j] + az + ebz);
                float nn = tanhf(gi[2 * HD + j] + r * (an + ebn));
                float hn = (1.0f - zg) * nn + zg * s_h[j];
                hbuf[q * HH + grp * HD + j] = hn;
                g_enc_out[t * HH + grp * HD + j] = hn;
            }
        }
        gbar_n(&g_barE[grp], 20, tgtE);
    }

    // full-grid barrier: both encoder chains complete
    gbar_n(&g_bar, P_CTAS, tgt);

    // ---- preload decoder weights ----
    float dbhr = 0, dbhz = 0, dbhn = 0, dbir = 0, dbiz = 0, dbin = 0;
    if (isGate) {
        const float* Wh = dir ? decWhh_b : decWhh_f;
        const float* Wi = dir ? decWih_b : decWih_f;
#pragma unroll
        for (int i = 0; i < 10; i++) {
            int k = lane + 32 * i;
            bool ok = k < HD;
            wA[i]      = ok ? Wh[j * HD + k] : 0.0f;
            wA[10 + i] = ok ? Wh[(HD + j) * HD + k] : 0.0f;
            wA[20 + i] = ok ? Wh[(2 * HD + j) * HD + k] : 0.0f;
            wB[i]      = ok ? Wi[j * EE + k] : 0.0f;
            wB[10 + i] = ok ? Wi[(EE + j) * EE + k] : 0.0f;
            wB[20 + i] = ok ? Wi[(2 * EE + j) * EE + k] : 0.0f;
        }
        const float* bh = dir ? decbhh_b : decbhh_f;
        const float* bi = dir ? decbih_b : decbih_f;
        dbhr = bh[j]; dbhz = bh[HD + j]; dbhn = bh[2 * HD + j];
        dbir = bi[j]; dbiz = bi[HD + j]; dbin = bi[2 * HD + j];
    }

    // ======== VAE phase 1: mean, logv, z ========
    for (int task = gw; task < LL * ZZ; task += P_WARPS) {
        int l = task / ZZ, zi = task % ZZ;
        float am = 0, av = 0;
        for (int k = lane; k < HH; k += 32) {
            float e = __ldcg(g_enc_out + l * HH + k);
            am = fmaf(h2m_W[zi * HH + k], e, am);
            av = fmaf(h2v_W[zi * HH + k], e, av);
        }
        am = wsum(am); av = wsum(av);
        if (lane == 0) {
            am += h2m_b[zi]; av += h2v_b[zi];
            out[OFF_MEAN + l * ZZ + zi] = am;
            out[OFF_LOGV + l * ZZ + zi] = av;
            g_z[l * ZZ + zi] = eps[l * ZZ + zi] * expf(0.5f * av) + am;
        }
    }
    gbar_n(&g_bar, P_CTAS, tgt);

    // ======== VAE phase 2: M = z @ C^T + d ========
    for (int task = gw; task < LL * EE; task += P_WARPS) {
        int l = task / EE, e = task % EE;
        float a = 0;
#pragma unroll
        for (int i = 0; i < 4; i++) {
            int k = lane + 32 * i;
            if (k < ZZ) a = fmaf(__ldcg(g_z + l * ZZ + k), g_C[e * ZZ + k], a);
        }
        a = wsum(a);
        if (lane == 0) g_M[l * EE + e] = a + g_d[e];
    }
    gbar_n(&g_bar, P_CTAS, tgt);

    // stage M into SMEM once
    for (int i = tid; i < LL * EE; i += P_THREADS) s_M[i] = __ldcg(g_M + i);

    // ======== decoder: 60 steps, 1 barrier each ========
    for (int t = 0; t < T_OUT; t++) {
        const int p = t & 1, q = p ^ 1;
        for (int i = tid; i < HH; i += P_THREADS) s_h[i] = __ldcg(&hbuf[p * HH + i]);  // FIXED: full 600 load
        __syncthreads();

        // attention scores (all 16 warps, redundant per CTA)
        const float4* sh4 = (const float4*)s_h;
#pragma unroll
        for (int rr = 0; rr < 4; rr++) {
            int l = warp + 16 * rr;
            if (l < LL) {
                const float4* aw4 = (const float4*)(attn_W + l * 900 + EE);
                float a = 0;
#pragma unroll
                for (int i = 0; i < 5; i++) {
                    int c = lane + 32 * i;
                    if (c < 150) {
                        float4 w = aw4[c];
                        float4 h4 = sh4[c];
                        a = fmaf(w.x, h4.x, fmaf(w.y, h4.y, fmaf(w.z, h4.z, fmaf(w.w, h4.w, a))));
                    }
                }
                a = wsum(a);
                if (lane == 0) s_s[l] = a + g_attn_x[t * LL + l];
            }
        }
        __syncthreads();

        // warp 0: softmax; gate warps: gh concurrently
        float ghr = 0, ghz = 0, ghn = 0;
        if (warp == 0) {
            float v0 = s_s[lane];
            float v1 = (lane + 32 < LL) ? s_s[lane + 32] : -1e30f;
            float m = wmax(fmaxf(v0, v1));
            float e0 = expf(v0 - m);
            float e1 = (lane + 32 < LL) ? expf(v1 - m) : 0.0f;
            float inv = 1.0f / wsum(e0 + e1);
            s_aw[lane] = e0 * inv;
            if (lane + 32 < LL) s_aw[lane + 32] = e1 * inv;
        } else {
            const float* hs = s_h + dir * HD;
            float ar = 0, az = 0, an = 0;
#pragma unroll
            for (int i = 0; i < 10; i++) {
                int k = lane + 32 * i;
                if (k < HD) {
                    float hv = hs[k];
                    ar = fmaf(wA[i], hv, ar);
                    az = fmaf(wA[10 + i], hv, az);
                    an = fmaf(wA[20 + i], hv, an);
                }
            }
            ar = wsum(ar); az = wsum(az); an = wsum(an);
            ghr = ar + dbhr; ghz = az + dbhz; ghn = an + dbhn;
        }
        __syncthreads();

        // o = relu(comb_x + aw @ M)
        if (tid < EE) {
            float acc = g_comb_x[t * EE + tid];
#pragma unroll
            for (int l = 0; l < LL; l++) acc = fmaf(s_aw[l], s_M[l * EE + tid], acc);
            s_o[tid] = fmaxf(acc, 0.0f);
        }
        __syncthreads();

        // gates
        if (isGate) {
            float br = 0, bz = 0, bn = 0;
#pragma unroll
            for (int i = 0; i < 10; i++) {
                int k = lane + 32 * i;
                if (k < EE) {
                    float ov = s_o[k];
                    br = fmaf(wB[i], ov, br);
                    bz = fmaf(wB[10 + i], ov, bz);
                    bn = fmaf(wB[20 + i], ov, bn);
                }
            }
            br = wsum(br); bz = wsum(bz); bn = wsum(bn);
            if (lane == 0) {
                float r = sigm(br + dbir + ghr);
                float zg = sigm(bz + dbiz + ghz);
                float nn = tanhf(bn + dbin + r * ghn);
                float hn = (1.0f - zg) * nn + zg * s_h[dir * HD + j];
                hbuf[q * HH + dir * HD + j] = hn;
                g_hT[(dir * HD + j) * 64 + t] = hn;
            }
        }
        gbar_n(&g_bar, P_CTAS, tgt);
    }
}

// ---------------- output GEMM with packed f32x2 ----------------
#define TBLK 20
#define NPAIR 10
__global__ __launch_bounds__(256) void out_gemm_kernel(
    const float* __restrict__ out_W, const float* __restrict__ out_b)
{
    __shared__ unsigned long long s_ht[600 * NPAIR];  // 48 KB
    int bv = blockIdx.x / 3, tb = blockIdx.x % 3;
    int t0 = tb * TBLK;

    for (int i = threadIdx.x; i < 600 * NPAIR; i += 256) {
        int k = i / NPAIR, m = i % NPAIR;
        float2 hv = *(const float2*)(g_hT + k * 64 + t0 + 2 * m);
        s_ht[i] = packf2(hv.x, hv.y);
    }
    __syncthreads();

    int v0 = bv * 512 + threadIdx.x;
    int v1 = v0 + 256;
    bool ok0 = v0 < VV, ok1 = v1 < VV;
    const float4* w0p = (const float4*)(out_W + (long)(ok0 ? v0 : 0) * HH);
    const float4* w1p = (const float4*)(out_W + (long)(ok1 ? v1 : 0) * HH);
    float b0 = out_b[ok0 ? v0 : 0];
    float b1 = out_b[ok1 ? v1 : 0];

    unsigned long long acc0[NPAIR], acc1[NPAIR];
#pragma unroll
    for (int m = 0; m < NPAIR; m++) {
        acc0[m] = packf2(b0, b0);
        acc1[m] = packf2(b1, b1);
    }

#pragma unroll 1
    for (int k4 = 0; k4 < 150; k4++) {
        float4 wa = w0p[k4];
        float4 wb = w1p[k4];
        unsigned long long wa2[4], wb2[4];
        wa2[0] = packf2(wa.x, wa.x); wa2[1] = packf2(wa.y, wa.y);
        wa2[2] = packf2(wa.z, wa.z); wa2[3] = packf2(wa.w, wa.w);
        wb2[0] = packf2(wb.x, wb.x); wb2[1] = packf2(wb.y, wb.y);
        wb2[2] = packf2(wb.z, wb.z); wb2[3] = packf2(wb.w, wb.w);
#pragma unroll
        for (int kk = 0; kk < 4; kk++) {
            const unsigned long long* hp = s_ht + (k4 * 4 + kk) * NPAIR;
#pragma unroll
            for (int m = 0; m < NPAIR; m++) {
                unsigned long long hv = hp[m];
                ffma2(acc0[m], wa2[kk], hv);
                ffma2(acc1[m], wb2[kk], hv);
            }
        }
    }

#pragma unroll
    for (int m = 0; m < NPAIR; m++) {
        float2 r0 = unpackf2(acc0[m]);
        float2 r1 = unpackf2(acc1[m]);
        int t = t0 + 2 * m;
        if (ok0) {
            g_logits[(long)t * VV + v0] = r0.x;
            g_logits[(long)(t + 1) * VV + v0] = r0.y;
        }
        if (ok1) {
            g_logits[(long)t * VV + v1] = r1.x;
            g_logits[(long)(t + 1) * VV + v1] = r1.y;
        }
    }
}

// ---------------- log_softmax per row ----------------
__global__ void lsm_kernel(float* __restrict__ out) {
    const int t = blockIdx.x;
    const float* row = g_logits + (long)t * VV;
    float* orow = out + (long)t * VV;
    __shared__ float sred[32];
    __shared__ float s_base;
    const int tid = threadIdx.x;
    const int nw = blockDim.x >> 5;

    float m = -3.4e38f;
    for (int v = tid; v < VV; v += blockDim.x) m = fmaxf(m, row[v]);
    m = wmax(m);
    if ((tid & 31) == 0) sred[tid >> 5] = m;
    __syncthreads();
    if (tid < 32) {
        float mm = (tid < nw) ? sred[tid] : -3.4e38f;
        mm = wmax(mm);
        if (tid == 0) sred[0] = mm;
    }
    __syncthreads();
    m = sred[0];
    __syncthreads();

    float ssum = 0.0f;
    for (int v = tid; v < VV; v += blockDim.x) ssum += expf(row[v] - m);
    ssum = wsum(ssum);
    if ((tid & 31) == 0) sred[tid >> 5] = ssum;
    __syncthreads();
    if (tid < 32) {
        float ss = (tid < nw) ? sred[tid] : 0.0f;
        ss = wsum(ss);
        if (tid == 0) s_base = m + logf(ss);
    }
    __syncthreads();
    float base = s_base;
    for (int v = tid; v < VV; v += blockDim.x) orow[v] = row[v] - base;
}

extern "C" void kernel_launch(void* const* d_in, const int* in_sizes, int n_in,
                              void* d_out, int out_size) {
    const int* input = (const int*)d_in[0];
    const int* target = (const int*)d_in[1];
    const float* eps = (const float*)d_in[2];
    const float* emb = (const float*)d_in[3];
    const float* encWih_f = (const float*)d_in[4];
    const float* encWhh_f = (const float*)d_in[5];
    const float* encbih_f = (const float*)d_in[6];
    const float* encbhh_f = (const float*)d_in[7];
    const float* encWih_b = (const float*)d_in[8];
    const float* encWhh_b = (const float*)d_in[9];
    const float* encbih_b = (const float*)d_in[10];
    const float* encbhh_b = (const float*)d_in[11];
    const float* decWih_f = (const float*)d_in[12];
    const float* decWhh_f = (const float*)d_in[13];
    const float* decbih_f = (const float*)d_in[14];
    const float* decbhh_f = (const float*)d_in[15];
    const float* decWih_b = (const float*)d_in[16];
    const float* decWhh_b = (const float*)d_in[17];
    const float* decbih_b = (const float*)d_in[18];
    const float* decbhh_b = (const float*)d_in[19];
    const float* h2m_W = (const float*)d_in[20];
    const float* h2m_b = (const float*)d_in[21];
    const float* h2v_W = (const float*)d_in[22];
    const float* h2v_b = (const float*)d_in[23];
    const float* l2h_W = (const float*)d_in[24];
    const float* l2h_b = (const float*)d_in[25];
    const float* attn_W = (const float*)d_in[26];
    const float* attn_b = (const float*)d_in[27];
    const float* comb_W = (const float*)d_in[28];
    const float* comb_b = (const float*)d_in[29];
    const float* out_W = (const float*)d_in[30];
    const float* out_b = (const float*)d_in[31];
    float* out = (float*)d_out;

    cudaFuncSetAttribute(seq_kernel, cudaFuncAttributeMaxDynamicSharedMemorySize,
                         SEQ_SMEM_BYTES);

    init_kernel<<<1, 256>>>();
    transpose_l2h<<<(ZZ * HH + 255) / 256, 256>>>(l2h_W);
    prepC_kernel<<<(PC_TASKS + 7) / 8, 256>>>(comb_W, l2h_b);
    prepass_kernel<<<(PP_WARPS + 7) / 8, 256>>>(input, target, emb,
                                                encWih_f, encbih_f, encWih_b, encbih_b,
                                                attn_W, attn_b, comb_W, comb_b);
    seq_kernel<<<P_CTAS, P_THREADS, SEQ_SMEM_BYTES>>>(eps,
                                      encWhh_f, encbhh_f, encWhh_b, encbhh_b,
                                      decWih_f, decWhh_f, decbih_f, decbhh_f,
                                      decWih_b, decWhh_b, decbih_b, decbhh_b,
                                      h2m_W, h2m_b, h2v_W, h2v_b,
                                      attn_W, out);
    out_gemm_kernel<<<((VV + 511) / 512) * 3, 256>>>(out_W, out_b);
    lsm_kernel<<<T_OUT, 1024>>>(out);
}